// round 13
// baseline (speedup 1.0000x reference)
#include <cuda_runtime.h>
#include <cuda_bf16.h>
#include <cstdint>

#define NEGINF -1e9f
#define SWZ(x) ((x) ^ (((x) >> 3) & 0x70))
#define LOG2E 1.4426950408889634f
#define LN2   0.6931471805599453f

// ---------- device scratch ----------
__device__ __align__(16) __nv_bfloat16 g_A[(size_t)16384 * 512];   // (t*32+n, k), 32*f/||f||
__device__ __align__(16) __nv_bfloat16 g_B[(size_t)1408 * 512];    // (c, k); rows>=1296 stay 0
__device__ __align__(16) uint8_t g_colmap[32 * 1296];              // value -> state slot + 1
__device__ float   g_psum[(size_t)16384 * 44];
__device__ float   g_lpraw[(size_t)16384 * 64];                    // gathered logits by slot
__device__ __align__(16) float g_lp[(size_t)32 * 512 * 64];        // (n,t,l) log2-probs
__device__ float   g_nll[32];
__device__ int     g_done;

__device__ __forceinline__ uint32_t sm2u(const void* p) {
    uint32_t a;
    asm("{ .reg .u64 t; cvta.to.shared.u64 t, %1; cvt.u32.u64 %0, t; }" : "=r"(a) : "l"(p));
    return a;
}
#define CPA16(d, s) asm volatile("cp.async.cg.shared.global [%0], [%1], 16;" :: "r"(d), "l"(s) : "memory")
__device__ __forceinline__ void ldmx4(uint32_t* r, uint32_t a) {
    asm volatile("ldmatrix.sync.aligned.m8n8.x4.shared.b16 {%0,%1,%2,%3}, [%4];"
        : "=r"(r[0]), "=r"(r[1]), "=r"(r[2]), "=r"(r[3]) : "r"(a));
}
__device__ __forceinline__ void mma16816(float* c, const uint32_t* a, uint32_t b0, uint32_t b1) {
    asm volatile("mma.sync.aligned.m16n8k16.row.col.f32.bf16.bf16.f32 "
        "{%0,%1,%2,%3},{%4,%5,%6,%7},{%8,%9},{%0,%1,%2,%3};"
        : "+f"(c[0]), "+f"(c[1]), "+f"(c[2]), "+f"(c[3])
        : "r"(a[0]), "r"(a[1]), "r"(a[2]), "r"(a[3]), "r"(b0), "r"(b1));
}
__device__ __forceinline__ float ex2f(float x) { float r; asm("ex2.approx.f32 %0, %1;" : "=f"(r) : "f"(x)); return r; }
__device__ __forceinline__ float lg2f(float x) { float r; asm("lg2.approx.f32 %0, %1;" : "=f"(r) : "f"(x)); return r; }

// ---------- K1: merged prep ----------
// blocks 0..40  : W columns [b*32, b*32+32): col norms + transpose + bf16
// blocks 41..2088: feats rows; blocks 41..72 also build colmap for seq b-41
__global__ void __launch_bounds__(256) prep_kernel(const float* __restrict__ w,
                                                   const float* __restrict__ f,
                                                   const int* __restrict__ labeling) {
    const int bid = blockIdx.x;
    if (bid < 41) {
        __shared__ float sp[8][33];
        __shared__ float tile[32][33];
        __shared__ float sinv[32];
        int tx = threadIdx.x & 31, ty = threadIdx.x >> 5;   // (32, 8)
        int c0 = bid * 32;
        int c = c0 + tx;
        // pass 1: column sum-of-squares
        float s = 0.f;
        if (c < 1296) {
            #pragma unroll 8
            for (int i = 0; i < 64; i++) {
                float v = w[(size_t)(ty + i * 8) * 1296 + c];
                s += v * v;
            }
        }
        sp[ty][tx] = s;
        __syncthreads();
        if (ty == 0) {
            float t = 0.f;
            #pragma unroll
            for (int i = 0; i < 8; i++) t += sp[i][tx];
            sinv[tx] = rsqrtf(t);
        }
        __syncthreads();
        // pass 2: transpose + normalize -> bf16 (L2-hot)
        for (int k0 = 0; k0 < 512; k0 += 32) {
            #pragma unroll
            for (int i = 0; i < 4; i++) {
                int k = k0 + ty + i * 8;
                tile[ty + i * 8][tx] = (c < 1296) ? w[(size_t)k * 1296 + c] : 0.f;
            }
            __syncthreads();
            #pragma unroll
            for (int i = 0; i < 4; i++) {
                int cc = c0 + ty + i * 8, k = k0 + tx;
                if (cc < 1296)
                    g_B[(size_t)cc * 512 + k] = __float2bfloat16(tile[tx][ty + i * 8] * sinv[ty + i * 8]);
            }
            __syncthreads();
        }
        return;
    }

    // ---- feats path ----
    const int fb = bid - 41;
    if (fb == 0 && threadIdx.x == 0) g_done = 0;
    int gw = (fb * 256 + threadIdx.x) >> 5;
    int lane = threadIdx.x & 31;
    const float2* row = (const float2*)(f + (size_t)gw * 512);
    float2 v[8]; float s = 0.f;
    #pragma unroll
    for (int j = 0; j < 8; j++) { v[j] = row[j * 32 + lane]; s += v[j].x * v[j].x + v[j].y * v[j].y; }
    #pragma unroll
    for (int o = 16; o > 0; o >>= 1) s += __shfl_xor_sync(0xffffffffu, s, o);
    float sc = 32.f * rsqrtf(s);
    __nv_bfloat162* dst = (__nv_bfloat162*)(g_A + (size_t)gw * 512);
    #pragma unroll
    for (int j = 0; j < 8; j++) dst[j * 32 + lane] = __floats2bfloat162_rn(v[j].x * sc, v[j].y * sc);

    if (fb < 32) {
        int n = fb;
        uint32_t* row32 = (uint32_t*)(g_colmap + n * 1296);
        for (int i = threadIdx.x; i < 324; i += 256) row32[i] = 0;
        __syncthreads();
        if (threadIdx.x == 0) {
            uint8_t* r8 = g_colmap + n * 1296;
            r8[0] = 1;
            for (int l = 1; l < 61; l += 2) r8[labeling[n * 30 + (l >> 1)]] = (uint8_t)(l + 1);
        }
    }
}

// ---------- K2: HMMA GEMM (R4 mainloop) + smem-colmap gather epilogue -------
__device__ __forceinline__ void load_stage(uint32_t sb, int st, int m0, int c0, int kc, int tid) {
    uint32_t abase = sb + (unsigned)st * 32768u;
    uint32_t bbase = abase + 16384u;
    #pragma unroll
    for (int it = 0; it < 8; it++) {
        int i = tid + it * 256;
        int row = i >> 3, ch = i & 7;
        uint32_t off = SWZ((uint32_t)((row & 127) * 128 + ch * 16));
        const char* src;
        uint32_t dst;
        if (row < 128) {
            src = (const char*)(g_A + ((size_t)(m0 + row)) * 512 + kc * 64) + ch * 16;
            dst = abase + off;
        } else {
            src = (const char*)(g_B + ((size_t)(c0 + row - 128)) * 512 + kc * 64) + ch * 16;
            dst = bbase + off;
        }
        CPA16(dst, src);
    }
    asm volatile("cp.async.commit_group;" ::: "memory");
}

__global__ void __launch_bounds__(256, 2) gemm_kernel() {
    extern __shared__ __align__(128) char smem[];   // [0,64K): stages, [64K, 64K+4224): colmap
    uint32_t sb = sm2u(smem);
    const int tid = threadIdx.x;
    const int lane = tid & 31, w = tid >> 5;
    const int warp_m = w >> 2, warp_n = w & 3;
    const int m0 = blockIdx.y * 128, c0 = blockIdx.x * 128;

    // preload this CTA's colmap slice into the dedicated smem region (pitch 132)
    {
        int n = tid >> 3, j = tid & 7;
        int off = c0 + j * 16;
        uint4 v = make_uint4(0u, 0u, 0u, 0u);
        if (off + 16 <= 1296)
            v = *(const uint4*)(g_colmap + (size_t)n * 1296 + off);
        uint32_t* d = (uint32_t*)(smem + 65536 + n * 132 + j * 16);
        d[0] = v.x; d[1] = v.y; d[2] = v.z; d[3] = v.w;
    }

    float acc[4][4][4];
    #pragma unroll
    for (int i = 0; i < 4; i++)
        #pragma unroll
        for (int j = 0; j < 4; j++)
            #pragma unroll
            for (int q = 0; q < 4; q++) acc[i][j][q] = 0.f;

    const int rowA = warp_m * 64 + (lane & 15);
    const uint32_t aBase0 = (uint32_t)(rowA * 128) + ((((lane >> 4) ^ lane) & 1) << 4);
    const int rowB = warp_n * 32 + (lane & 7) + (((lane >> 4) & 1) << 3);
    const uint32_t bBase0 = (uint32_t)(rowB * 128) + ((((lane >> 3) ^ lane) & 1) << 4);
    const uint32_t kx = (uint32_t)(lane & 6) << 4;

    load_stage(sb, 0, m0, c0, 0, tid);

    for (int kc = 0; kc < 8; kc++) {
        if (kc < 7) {
            load_stage(sb, (kc + 1) & 1, m0, c0, kc + 1, tid);
            asm volatile("cp.async.wait_group 1;" ::: "memory");
        } else {
            asm volatile("cp.async.wait_group 0;" ::: "memory");
        }
        __syncthreads();
        uint32_t astage = sb + (unsigned)(kc & 1) * 32768u;
        uint32_t bstage = astage + 16384u;
        #pragma unroll
        for (int ks = 0; ks < 4; ks++) {
            uint32_t ko = ((uint32_t)(ks << 5)) ^ kx;
            uint32_t a[4][4], bfr[8];
            #pragma unroll
            for (int mi = 0; mi < 4; mi++)
                ldmx4(a[mi], astage + aBase0 + mi * 2048 + ko);
            ldmx4(&bfr[0], bstage + bBase0 + ko);
            ldmx4(&bfr[4], bstage + bBase0 + 2048 + ko);
            #pragma unroll
            for (int mi = 0; mi < 4; mi++)
                #pragma unroll
                for (int nj = 0; nj < 4; nj++)
                    mma16816(acc[mi][nj], a[mi], bfr[nj * 2], bfr[nj * 2 + 1]);
        }
        __syncthreads();
    }

    const int tq = lane >> 2, qi = lane & 3;
    const float EC = -32.f * LOG2E;
    const bool full = (c0 + 128 <= 1296);
    #pragma unroll
    for (int mi = 0; mi < 4; mi++) {
        #pragma unroll
        for (int half = 0; half < 2; half++) {
            int m = m0 + warp_m * 64 + mi * 16 + tq + half * 8;
            const uint8_t* cm = (const uint8_t*)smem + 65536 + (m & 31) * 132 - c0;
            float s = 0.f;
            if (full) {
                #pragma unroll
                for (int nj = 0; nj < 4; nj++) {
                    int c = c0 + warp_n * 32 + nj * 8 + qi * 2;
                    float x0 = acc[mi][nj][half * 2 + 0];
                    float x1 = acc[mi][nj][half * 2 + 1];
                    s += ex2f(fmaf(x0, LOG2E, EC));
                    s += ex2f(fmaf(x1, LOG2E, EC));
                    uint8_t v0 = cm[c], v1 = cm[c + 1];
                    if (v0) g_lpraw[(size_t)m * 64 + v0 - 1] = x0;
                    if (v1) g_lpraw[(size_t)m * 64 + v1 - 1] = x1;
                }
            } else {
                #pragma unroll
                for (int nj = 0; nj < 4; nj++) {
                    int c = c0 + warp_n * 32 + nj * 8 + qi * 2;
                    float x0 = acc[mi][nj][half * 2 + 0];
                    float x1 = acc[mi][nj][half * 2 + 1];
                    if (c < 1296) {
                        s += ex2f(fmaf(x0, LOG2E, EC));
                        uint8_t v = cm[c];
                        if (v) g_lpraw[(size_t)m * 64 + v - 1] = x0;
                    }
                    if (c + 1 < 1296) {
                        s += ex2f(fmaf(x1, LOG2E, EC));
                        uint8_t v = cm[c + 1];
                        if (v) g_lpraw[(size_t)m * 64 + v - 1] = x1;
                    }
                }
            }
            s += __shfl_xor_sync(0xffffffffu, s, 1);
            s += __shfl_xor_sync(0xffffffffu, s, 2);
            if (qi == 0)
                g_psum[(size_t)m * 44 + blockIdx.x * 4 + warp_n] = s;
        }
    }
}

// ---------- K3: finalize lp = (gathered - lse) * log2e ----------
__global__ void finalize_kernel(const int* __restrict__ labeling) {
    int gw = blockIdx.x * 8 + (threadIdx.x >> 5);   // gw = t*32 + n
    int lane = threadIdx.x & 31;
    int t = gw >> 5, n = gw & 31;
    const float* P = g_psum + (size_t)gw * 44;
    float p = (lane < 22) ? (P[lane] + P[lane + 22]) : 0.f;
    #pragma unroll
    for (int o = 16; o > 0; o >>= 1) p += __shfl_xor_sync(0xffffffffu, p, o);
    float lse = 32.f + logf(p);
    float* dst = g_lp + ((size_t)n * 512 + t) * 64;
    const float* raw = g_lpraw + (size_t)gw * 64;
    #pragma unroll
    for (int r = 0; r < 2; r++) {
        int l = lane + r * 32;
        if (l < 61) {
            int ext = (l & 1) ? labeling[n * 30 + (l >> 1)] : 0;
            int v = g_colmap[n * 1296 + ext];
            dst[l] = (raw[v - 1] - lse) * LOG2E;
        } else if (l < 64) dst[l] = NEGINF;
    }
}

// ---------- K4: CTC log2-domain, smem lp, fused deterministic final sum -----
__global__ void __launch_bounds__(256) ctc_kernel(const int* __restrict__ labeling,
                                                  const int* __restrict__ in_lens,
                                                  const int* __restrict__ lab_lens,
                                                  float* __restrict__ out) {
    extern __shared__ __align__(16) float2 slp[];   // [512][32] float2 = 128 KB
    const int n = blockIdx.x;
    const int tid = threadIdx.x;
    uint32_t sbase = sm2u(slp);
    const char* src = (const char*)(g_lp + (size_t)n * 512 * 64);
    #pragma unroll
    for (int it = 0; it < 32; it++) {
        int i = tid + it * 256;
        CPA16(sbase + i * 16, src + i * 16);
    }
    asm volatile("cp.async.commit_group;" ::: "memory");
    asm volatile("cp.async.wait_group 0;" ::: "memory");
    __syncthreads();
    if (tid >= 32) return;

    const int l = tid;
    int labv = (l < 30) ? labeling[n * 30 + l] : 0;
    int labp = (l >= 1 && l <= 30) ? labeling[n * 30 + l - 1] : 0;
    const bool skip = (l >= 1 && l <= 29 && labv != labp);
    const int Tlen = in_lens[n];

    float2 v0 = slp[l];
    float lo = (l == 0) ? v0.x : NEGINF;
    float hi = (l == 0) ? v0.y : NEGINF;
    float2 lp = slp[32 + l];
    for (int t = 1; t < Tlen; t++) {
        int tn = (t + 1 < 512) ? t + 1 : 511;
        float2 nxt = slp[tn * 32 + l];
        float hp = __shfl_up_sync(0xffffffffu, hi, 1);
        if (l == 0) hp = NEGINF;
        float m1 = fmaxf(lo, hp);
        float nlo = m1 + lg2f(ex2f(lo - m1) + ex2f(hp - m1)) + lp.x;
        float a3 = skip ? hp : NEGINF;
        float m2 = fmaxf(hi, fmaxf(lo, a3));
        float nhi = m2 + lg2f(ex2f(hi - m2) + ex2f(lo - m2) + ex2f(a3 - m2)) + lp.y;
        lo = nlo; hi = nhi; lp = nxt;
    }
    int lab = lab_lens[n];
    float x = __shfl_sync(0xffffffffu, lo, lab);       // alpha[2*lab]
    float y = __shfl_sync(0xffffffffu, hi, lab - 1);   // alpha[2*lab-1]
    if (l == 0) {
        float mx = fmaxf(x, y);
        g_nll[n] = -(mx + lg2f(ex2f(x - mx) + ex2f(y - mx))) * LN2;
        __threadfence();
        int ticket = atomicAdd(&g_done, 1);
        if (ticket == 31) {                             // last block: fixed-order sum
            float s = 0.f;
            #pragma unroll
            for (int k = 0; k < 32; k++) s += g_nll[k];
            out[0] = s;
        }
    }
}

// ---------- launch ----------
extern "C" void kernel_launch(void* const* d_in, const int* in_sizes, int n_in,
                              void* d_out, int out_size) {
    const float* feats = (const float*)d_in[0];
    const float* weight = (const float*)d_in[1];
    const int* labeling = (const int*)d_in[2];
    const int* logit_lgts = (const int*)d_in[3];
    const int* labeling_lgts = (const int*)d_in[4];
    float* out = (float*)d_out;

    cudaFuncSetAttribute(gemm_kernel, cudaFuncAttributeMaxDynamicSharedMemorySize, 69888);
    cudaFuncSetAttribute(ctc_kernel, cudaFuncAttributeMaxDynamicSharedMemorySize, 131072);

    prep_kernel<<<2089, 256>>>(weight, feats, labeling);
    gemm_kernel<<<dim3(11, 128), 256, 69888>>>();
    finalize_kernel<<<2048, 256>>>(labeling);
    ctc_kernel<<<32, 256, 131072>>>(labeling, logit_lgts, labeling_lgts, out);
}

// round 14
// speedup vs baseline: 1.0899x; 1.0899x over previous
#include <cuda_runtime.h>
#include <cuda_bf16.h>
#include <cstdint>

#define NEGINF -1e9f
#define SWZ(x) ((x) ^ (((x) >> 3) & 0x70))
#define LOG2E 1.4426950408889634f
#define LN2   0.6931471805599453f

// ---------- device scratch ----------
__device__ __align__(16) __nv_bfloat16 g_A[(size_t)16384 * 512];   // (t*32+n, k), 32*f/||f||
__device__ __align__(16) __nv_bfloat16 g_B[(size_t)1408 * 512];    // (c, k); rows>=1296 stay 0
__device__ float   g_part[8 * 1296];
__device__ __align__(16) uint8_t g_colmap[32 * 1296];              // value -> state slot + 1
__device__ float   g_psum[(size_t)16384 * 44];
__device__ float   g_lpraw[(size_t)16384 * 64];                    // gathered logits by slot
__device__ __align__(16) float g_lp[(size_t)32 * 512 * 64];        // (n,t,l) log2-probs
__device__ float   g_nll[32];
__device__ int     g_done;

__device__ __forceinline__ uint32_t sm2u(const void* p) {
    uint32_t a;
    asm("{ .reg .u64 t; cvta.to.shared.u64 t, %1; cvt.u32.u64 %0, t; }" : "=r"(a) : "l"(p));
    return a;
}
#define CPA16(d, s) asm volatile("cp.async.cg.shared.global [%0], [%1], 16;" :: "r"(d), "l"(s) : "memory")
__device__ __forceinline__ void ldmx4(uint32_t* r, uint32_t a) {
    asm volatile("ldmatrix.sync.aligned.m8n8.x4.shared.b16 {%0,%1,%2,%3}, [%4];"
        : "=r"(r[0]), "=r"(r[1]), "=r"(r[2]), "=r"(r[3]) : "r"(a));
}
__device__ __forceinline__ void mma16816(float* c, const uint32_t* a, uint32_t b0, uint32_t b1) {
    asm volatile("mma.sync.aligned.m16n8k16.row.col.f32.bf16.bf16.f32 "
        "{%0,%1,%2,%3},{%4,%5,%6,%7},{%8,%9},{%0,%1,%2,%3};"
        : "+f"(c[0]), "+f"(c[1]), "+f"(c[2]), "+f"(c[3])
        : "r"(a[0]), "r"(a[1]), "r"(a[2]), "r"(a[3]), "r"(b0), "r"(b1));
}
__device__ __forceinline__ float ex2f(float x) { float r; asm("ex2.approx.f32 %0, %1;" : "=f"(r) : "f"(x)); return r; }
__device__ __forceinline__ float lg2f(float x) { float r; asm("lg2.approx.f32 %0, %1;" : "=f"(r) : "f"(x)); return r; }

// ---------- K1: column sum-of-squares partials ----------
__global__ void colsum_kernel(const float* __restrict__ w) {
    __shared__ float sp[8][33];
    int c0 = blockIdx.x * 32, d0 = blockIdx.y * 64;
    int tx = threadIdx.x, ty = threadIdx.y;
    int c = c0 + tx;
    float s = 0.f;
    if (c < 1296) {
        #pragma unroll
        for (int i = 0; i < 8; i++) {
            float v = w[(size_t)(d0 + ty + i * 8) * 1296 + c];
            s += v * v;
        }
    }
    sp[ty][tx] = s;
    __syncthreads();
    if (ty == 0 && c < 1296) {
        float t = 0.f;
        #pragma unroll
        for (int i = 0; i < 8; i++) t += sp[i][tx];
        g_part[blockIdx.y * 1296 + c] = t;
    }
}

// ---------- K2: W transpose + normalize -> bf16 (c,k) ----------
__global__ void wtrans_kernel(const float* __restrict__ w) {
    __shared__ float tile[32][33];
    int c0 = blockIdx.x * 32, k0 = blockIdx.y * 32;
    int tx = threadIdx.x, ty = threadIdx.y;
    #pragma unroll
    for (int i = 0; i < 4; i++) {
        int c = c0 + tx, k = k0 + ty + i * 8;
        tile[ty + i * 8][tx] = (c < 1296) ? w[(size_t)k * 1296 + c] : 0.f;
    }
    __syncthreads();
    #pragma unroll
    for (int i = 0; i < 4; i++) {
        int c = c0 + ty + i * 8, k = k0 + tx;
        if (c < 1296) {
            float sum = 0.f;
            #pragma unroll
            for (int j = 0; j < 8; j++) sum += g_part[j * 1296 + c];
            g_B[(size_t)c * 512 + k] = __float2bfloat16(tile[tx][ty + i * 8] * rsqrtf(sum));
        }
    }
}

// ---------- K3: feats * 32/||f|| -> bf16 ; blocks 0-31 build colmap ----------
__global__ void fprep_kernel(const float* __restrict__ f, const int* __restrict__ labeling) {
    if (blockIdx.x == 0 && threadIdx.x == 0) g_done = 0;
    int gw = (blockIdx.x * blockDim.x + threadIdx.x) >> 5;
    int lane = threadIdx.x & 31;
    const float2* row = (const float2*)(f + (size_t)gw * 512);
    float2 v[8]; float s = 0.f;
    #pragma unroll
    for (int j = 0; j < 8; j++) { v[j] = row[j * 32 + lane]; s += v[j].x * v[j].x + v[j].y * v[j].y; }
    #pragma unroll
    for (int o = 16; o > 0; o >>= 1) s += __shfl_xor_sync(0xffffffffu, s, o);
    float sc = 32.f * rsqrtf(s);
    __nv_bfloat162* dst = (__nv_bfloat162*)(g_A + (size_t)gw * 512);
    #pragma unroll
    for (int j = 0; j < 8; j++) dst[j * 32 + lane] = __floats2bfloat162_rn(v[j].x * sc, v[j].y * sc);

    if (blockIdx.x < 32) {
        int n = blockIdx.x;
        uint32_t* row32 = (uint32_t*)(g_colmap + n * 1296);
        for (int i = threadIdx.x; i < 324; i += 256) row32[i] = 0;
        __syncthreads();
        if (threadIdx.x == 0) {
            uint8_t* r8 = g_colmap + n * 1296;
            r8[0] = 1;
            for (int l = 1; l < 61; l += 2) r8[labeling[n * 30 + (l >> 1)]] = (uint8_t)(l + 1);
        }
    }
}

// ---------- K4: HMMA GEMM (R4 mainloop) + smem-colmap gather epilogue -------
__device__ __forceinline__ void load_stage(uint32_t sb, int st, int m0, int c0, int kc, int tid) {
    uint32_t abase = sb + (unsigned)st * 32768u;
    uint32_t bbase = abase + 16384u;
    #pragma unroll
    for (int it = 0; it < 8; it++) {
        int i = tid + it * 256;
        int row = i >> 3, ch = i & 7;
        uint32_t off = SWZ((uint32_t)((row & 127) * 128 + ch * 16));
        const char* src;
        uint32_t dst;
        if (row < 128) {
            src = (const char*)(g_A + ((size_t)(m0 + row)) * 512 + kc * 64) + ch * 16;
            dst = abase + off;
        } else {
            src = (const char*)(g_B + ((size_t)(c0 + row - 128)) * 512 + kc * 64) + ch * 16;
            dst = bbase + off;
        }
        CPA16(dst, src);
    }
    asm volatile("cp.async.commit_group;" ::: "memory");
}

__global__ void __launch_bounds__(256, 2) gemm_kernel() {
    extern __shared__ __align__(128) char smem[];
    uint32_t sb = sm2u(smem);
    const int tid = threadIdx.x;
    const int lane = tid & 31, w = tid >> 5;
    const int warp_m = w >> 2, warp_n = w & 3;
    const int m0 = blockIdx.y * 128, c0 = blockIdx.x * 128;

    float acc[4][4][4];
    #pragma unroll
    for (int i = 0; i < 4; i++)
        #pragma unroll
        for (int j = 0; j < 4; j++)
            #pragma unroll
            for (int q = 0; q < 4; q++) acc[i][j][q] = 0.f;

    const int rowA = warp_m * 64 + (lane & 15);
    const uint32_t aBase0 = (uint32_t)(rowA * 128) + ((((lane >> 4) ^ lane) & 1) << 4);
    const int rowB = warp_n * 32 + (lane & 7) + (((lane >> 4) & 1) << 3);
    const uint32_t bBase0 = (uint32_t)(rowB * 128) + ((((lane >> 3) ^ lane) & 1) << 4);
    const uint32_t kx = (uint32_t)(lane & 6) << 4;

    load_stage(sb, 0, m0, c0, 0, tid);

    for (int kc = 0; kc < 8; kc++) {
        if (kc < 7) {
            load_stage(sb, (kc + 1) & 1, m0, c0, kc + 1, tid);
            asm volatile("cp.async.wait_group 1;" ::: "memory");
        } else {
            asm volatile("cp.async.wait_group 0;" ::: "memory");
        }
        __syncthreads();
        uint32_t astage = sb + (unsigned)(kc & 1) * 32768u;
        uint32_t bstage = astage + 16384u;
        #pragma unroll
        for (int ks = 0; ks < 4; ks++) {
            uint32_t ko = ((uint32_t)(ks << 5)) ^ kx;
            uint32_t a[4][4], bfr[8];
            #pragma unroll
            for (int mi = 0; mi < 4; mi++)
                ldmx4(a[mi], astage + aBase0 + mi * 2048 + ko);
            ldmx4(&bfr[0], bstage + bBase0 + ko);
            ldmx4(&bfr[4], bstage + bBase0 + 2048 + ko);
            #pragma unroll
            for (int mi = 0; mi < 4; mi++)
                #pragma unroll
                for (int nj = 0; nj < 4; nj++)
                    mma16816(acc[mi][nj], a[mi], bfr[nj * 2], bfr[nj * 2 + 1]);
        }
        __syncthreads();
    }

    // stage this CTA's colmap slice (32 seqs x 128 cols) into smem, pitch 132
    {
        int n = tid >> 3, j = tid & 7;
        int off = c0 + j * 16;
        uint4 v = make_uint4(0u, 0u, 0u, 0u);
        if (off + 16 <= 1296)
            v = *(const uint4*)(g_colmap + (size_t)n * 1296 + off);
        uint32_t* d = (uint32_t*)(smem + n * 132 + j * 16);
        d[0] = v.x; d[1] = v.y; d[2] = v.z; d[3] = v.w;
    }
    __syncthreads();

    const int tq = lane >> 2, qi = lane & 3;
    const float EC = -32.f * LOG2E;
    const bool full = (c0 + 128 <= 1296);
    #pragma unroll
    for (int mi = 0; mi < 4; mi++) {
        #pragma unroll
        for (int half = 0; half < 2; half++) {
            int m = m0 + warp_m * 64 + mi * 16 + tq + half * 8;
            const uint8_t* cm = (const uint8_t*)smem + (m & 31) * 132 - c0;
            float s = 0.f;
            if (full) {
                #pragma unroll
                for (int nj = 0; nj < 4; nj++) {
                    int c = c0 + warp_n * 32 + nj * 8 + qi * 2;
                    float x0 = acc[mi][nj][half * 2 + 0];
                    float x1 = acc[mi][nj][half * 2 + 1];
                    s += ex2f(fmaf(x0, LOG2E, EC));
                    s += ex2f(fmaf(x1, LOG2E, EC));
                    uint8_t v0 = cm[c], v1 = cm[c + 1];
                    if (v0) g_lpraw[(size_t)m * 64 + v0 - 1] = x0;
                    if (v1) g_lpraw[(size_t)m * 64 + v1 - 1] = x1;
                }
            } else {
                #pragma unroll
                for (int nj = 0; nj < 4; nj++) {
                    int c = c0 + warp_n * 32 + nj * 8 + qi * 2;
                    float x0 = acc[mi][nj][half * 2 + 0];
                    float x1 = acc[mi][nj][half * 2 + 1];
                    if (c < 1296) {
                        s += ex2f(fmaf(x0, LOG2E, EC));
                        uint8_t v = cm[c];
                        if (v) g_lpraw[(size_t)m * 64 + v - 1] = x0;
                    }
                    if (c + 1 < 1296) {
                        s += ex2f(fmaf(x1, LOG2E, EC));
                        uint8_t v = cm[c + 1];
                        if (v) g_lpraw[(size_t)m * 64 + v - 1] = x1;
                    }
                }
            }
            s += __shfl_xor_sync(0xffffffffu, s, 1);
            s += __shfl_xor_sync(0xffffffffu, s, 2);
            if (qi == 0)
                g_psum[(size_t)m * 44 + blockIdx.x * 4 + warp_n] = s;
        }
    }
}

// ---------- K5: finalize lp = (gathered - lse) * log2e ----------
__global__ void finalize_kernel(const int* __restrict__ labeling) {
    int gw = blockIdx.x * 8 + (threadIdx.x >> 5);   // gw = t*32 + n
    int lane = threadIdx.x & 31;
    int t = gw >> 5, n = gw & 31;
    const float* P = g_psum + (size_t)gw * 44;
    float p = (lane < 22) ? (P[lane] + P[lane + 22]) : 0.f;
    #pragma unroll
    for (int o = 16; o > 0; o >>= 1) p += __shfl_xor_sync(0xffffffffu, p, o);
    float lse = 32.f + logf(p);
    float* dst = g_lp + ((size_t)n * 512 + t) * 64;
    const float* raw = g_lpraw + (size_t)gw * 64;
    #pragma unroll
    for (int r = 0; r < 2; r++) {
        int l = lane + r * 32;
        if (l < 61) {
            int ext = (l & 1) ? labeling[n * 30 + (l >> 1)] : 0;
            int v = g_colmap[n * 1296 + ext];
            dst[l] = (raw[v - 1] - lse) * LOG2E;
        } else if (l < 64) dst[l] = NEGINF;
    }
}

// ---------- K6: CTC log2-domain, reduced-MUFU lsum, smem lp ----------
__global__ void __launch_bounds__(256) ctc_kernel(const int* __restrict__ labeling,
                                                  const int* __restrict__ in_lens,
                                                  const int* __restrict__ lab_lens,
                                                  float* __restrict__ out) {
    extern __shared__ __align__(16) float2 slp[];   // 513 rows x 32 float2 (row 512 scratch)
    const int n = blockIdx.x;
    const int tid = threadIdx.x;
    uint32_t sbase = sm2u(slp);
    const char* src = (const char*)(g_lp + (size_t)n * 512 * 64);
    #pragma unroll
    for (int it = 0; it < 32; it++) {
        int i = tid + it * 256;
        CPA16(sbase + i * 16, src + i * 16);
    }
    asm volatile("cp.async.commit_group;" ::: "memory");
    asm volatile("cp.async.wait_group 0;" ::: "memory");
    __syncthreads();
    if (tid >= 32) return;

    const int l = tid;
    int labv = (l < 30) ? labeling[n * 30 + l] : 0;
    int labp = (l >= 1 && l <= 30) ? labeling[n * 30 + l - 1] : 0;
    const bool skip = (l >= 1 && l <= 29 && labv != labp);
    const int Tlen = in_lens[n];

    float2 v0 = slp[l];
    float lo = (l == 0) ? v0.x : NEGINF;
    float hi = (l == 0) ? v0.y : NEGINF;
    float2 lp = slp[32 + l];
    const float2* prow = &slp[64 + l];              // row t+1 for t = 1
    for (int t = 1; t < Tlen; t++) {
        float2 nxt = *prow; prow += 32;             // prefetch (last iter reads scratch row)
        float hp = __shfl_up_sync(0xffffffffu, hi, 1);
        if (l == 0) hp = NEGINF;
        // nlo = lsum2(lo, hp): one term is exactly 1 after max-shift
        float mx1 = fmaxf(lo, hp), mn1 = fminf(lo, hp);
        float nlo = mx1 + lg2f(1.f + ex2f(mn1 - mx1)) + lp.x;
        // nhi = lsum3(hi, lo, a3): median/min network, max term is 1
        float a3 = skip ? hp : NEGINF;
        float mxhl = fmaxf(hi, lo), mnhl = fminf(hi, lo);
        float m2 = fmaxf(mxhl, a3);
        float md = fmaxf(mnhl, fminf(mxhl, a3));
        float mn = fminf(mnhl, a3);
        float nhi = m2 + lg2f(1.f + ex2f(md - m2) + ex2f(mn - m2)) + lp.y;
        lo = nlo; hi = nhi; lp = nxt;
    }
    int lab = lab_lens[n];
    float x = __shfl_sync(0xffffffffu, lo, lab);       // alpha[2*lab]
    float y = __shfl_sync(0xffffffffu, hi, lab - 1);   // alpha[2*lab-1]
    if (l == 0) {
        float mx = fmaxf(x, y), mnv = fminf(x, y);
        g_nll[n] = -(mx + lg2f(1.f + ex2f(mnv - mx))) * LN2;
        __threadfence();
        int ticket = atomicAdd(&g_done, 1);
        if (ticket == 31) {                             // last block: fixed-order sum
            float s = 0.f;
            #pragma unroll
            for (int k = 0; k < 32; k++) s += g_nll[k];
            out[0] = s;
        }
    }
}

// ---------- launch ----------
extern "C" void kernel_launch(void* const* d_in, const int* in_sizes, int n_in,
                              void* d_out, int out_size) {
    const float* feats = (const float*)d_in[0];
    const float* weight = (const float*)d_in[1];
    const int* labeling = (const int*)d_in[2];
    const int* logit_lgts = (const int*)d_in[3];
    const int* labeling_lgts = (const int*)d_in[4];
    float* out = (float*)d_out;

    cudaFuncSetAttribute(gemm_kernel, cudaFuncAttributeMaxDynamicSharedMemorySize, 65536);
    cudaFuncSetAttribute(ctc_kernel, cudaFuncAttributeMaxDynamicSharedMemorySize, 132096);

    colsum_kernel<<<dim3(41, 8), dim3(32, 8)>>>(weight);
    wtrans_kernel<<<dim3(41, 16), dim3(32, 8)>>>(weight);
    fprep_kernel<<<2048, 256>>>(feats, labeling);
    gemm_kernel<<<dim3(11, 128), 256, 65536>>>();
    finalize_kernel<<<2048, 256>>>(labeling);
    ctc_kernel<<<32, 256, 132096>>>(labeling, logit_lgts, labeling_lgts, out);
}

// round 15
// speedup vs baseline: 1.2315x; 1.1299x over previous
#include <cuda_runtime.h>
#include <cuda_bf16.h>
#include <cstdint>

#define NEGINF -1e9f
#define SWZ(x) ((x) ^ (((x) >> 3) & 0x70))
#define LOG2E 1.4426950408889634f
#define LN2   0.6931471805599453f

// ---------- device scratch ----------
__device__ __align__(16) __nv_bfloat16 g_A[(size_t)16384 * 512];   // (t*32+n, k), 32*f/||f||
__device__ __align__(16) __nv_bfloat16 g_B[(size_t)1408 * 512];    // (c, k); rows>=1296 stay 0
__device__ float   g_part[8 * 1296];
__device__ __align__(16) uint8_t g_colmap[32 * 1296];              // value -> state slot + 1
__device__ float   g_psum[(size_t)16384 * 44];
__device__ float   g_lpraw[(size_t)16384 * 64];                    // gathered logits by slot
__device__ __align__(16) float g_lp[(size_t)32 * 512 * 64];        // (n,t,l) log2-probs
__device__ float   g_nll[32];
__device__ int     g_done;

__device__ __forceinline__ uint32_t sm2u(const void* p) {
    uint32_t a;
    asm("{ .reg .u64 t; cvta.to.shared.u64 t, %1; cvt.u32.u64 %0, t; }" : "=r"(a) : "l"(p));
    return a;
}
#define CPA16(d, s) asm volatile("cp.async.cg.shared.global [%0], [%1], 16;" :: "r"(d), "l"(s) : "memory")
__device__ __forceinline__ void ldmx4(uint32_t* r, uint32_t a) {
    asm volatile("ldmatrix.sync.aligned.m8n8.x4.shared.b16 {%0,%1,%2,%3}, [%4];"
        : "=r"(r[0]), "=r"(r[1]), "=r"(r[2]), "=r"(r[3]) : "r"(a));
}
__device__ __forceinline__ void mma16816(float* c, const uint32_t* a, uint32_t b0, uint32_t b1) {
    asm volatile("mma.sync.aligned.m16n8k16.row.col.f32.bf16.bf16.f32 "
        "{%0,%1,%2,%3},{%4,%5,%6,%7},{%8,%9},{%0,%1,%2,%3};"
        : "+f"(c[0]), "+f"(c[1]), "+f"(c[2]), "+f"(c[3])
        : "r"(a[0]), "r"(a[1]), "r"(a[2]), "r"(a[3]), "r"(b0), "r"(b1));
}
__device__ __forceinline__ float ex2f(float x) { float r; asm("ex2.approx.f32 %0, %1;" : "=f"(r) : "f"(x)); return r; }
__device__ __forceinline__ float lg2f(float x) { float r; asm("lg2.approx.f32 %0, %1;" : "=f"(r) : "f"(x)); return r; }

// ---------- K1: column sum-of-squares partials ----------
__global__ void colsum_kernel(const float* __restrict__ w) {
    __shared__ float sp[8][33];
    int c0 = blockIdx.x * 32, d0 = blockIdx.y * 64;
    int tx = threadIdx.x, ty = threadIdx.y;
    int c = c0 + tx;
    float s = 0.f;
    if (c < 1296) {
        #pragma unroll
        for (int i = 0; i < 8; i++) {
            float v = w[(size_t)(d0 + ty + i * 8) * 1296 + c];
            s += v * v;
        }
    }
    sp[ty][tx] = s;
    __syncthreads();
    if (ty == 0 && c < 1296) {
        float t = 0.f;
        #pragma unroll
        for (int i = 0; i < 8; i++) t += sp[i][tx];
        g_part[blockIdx.y * 1296 + c] = t;
    }
}

// ---------- K2: W transpose + normalize -> bf16 (c,k) ----------
__global__ void wtrans_kernel(const float* __restrict__ w) {
    __shared__ float tile[32][33];
    int c0 = blockIdx.x * 32, k0 = blockIdx.y * 32;
    int tx = threadIdx.x, ty = threadIdx.y;
    #pragma unroll
    for (int i = 0; i < 4; i++) {
        int c = c0 + tx, k = k0 + ty + i * 8;
        tile[ty + i * 8][tx] = (c < 1296) ? w[(size_t)k * 1296 + c] : 0.f;
    }
    __syncthreads();
    #pragma unroll
    for (int i = 0; i < 4; i++) {
        int c = c0 + ty + i * 8, k = k0 + tx;
        if (c < 1296) {
            float sum = 0.f;
            #pragma unroll
            for (int j = 0; j < 8; j++) sum += g_part[j * 1296 + c];
            g_B[(size_t)c * 512 + k] = __float2bfloat16(tile[tx][ty + i * 8] * rsqrtf(sum));
        }
    }
}

// ---------- K3: feats * 32/||f|| -> bf16 ; blocks 0-31 build colmap ----------
__global__ void fprep_kernel(const float* __restrict__ f, const int* __restrict__ labeling) {
    if (blockIdx.x == 0 && threadIdx.x == 0) g_done = 0;
    int gw = (blockIdx.x * blockDim.x + threadIdx.x) >> 5;
    int lane = threadIdx.x & 31;
    const float2* row = (const float2*)(f + (size_t)gw * 512);
    float2 v[8]; float s = 0.f;
    #pragma unroll
    for (int j = 0; j < 8; j++) { v[j] = row[j * 32 + lane]; s += v[j].x * v[j].x + v[j].y * v[j].y; }
    #pragma unroll
    for (int o = 16; o > 0; o >>= 1) s += __shfl_xor_sync(0xffffffffu, s, o);
    float sc = 32.f * rsqrtf(s);
    __nv_bfloat162* dst = (__nv_bfloat162*)(g_A + (size_t)gw * 512);
    #pragma unroll
    for (int j = 0; j < 8; j++) dst[j * 32 + lane] = __floats2bfloat162_rn(v[j].x * sc, v[j].y * sc);

    if (blockIdx.x < 32) {
        int n = blockIdx.x;
        uint32_t* row32 = (uint32_t*)(g_colmap + n * 1296);
        for (int i = threadIdx.x; i < 324; i += 256) row32[i] = 0;
        __syncthreads();
        if (threadIdx.x == 0) {
            uint8_t* r8 = g_colmap + n * 1296;
            r8[0] = 1;
            for (int l = 1; l < 61; l += 2) r8[labeling[n * 30 + (l >> 1)]] = (uint8_t)(l + 1);
        }
    }
}

// ---------- K4: HMMA GEMM (R4 mainloop) + smem-colmap gather epilogue -------
__device__ __forceinline__ void load_stage(uint32_t sb, int st, int m0, int c0, int kc, int tid) {
    uint32_t abase = sb + (unsigned)st * 32768u;
    uint32_t bbase = abase + 16384u;
    #pragma unroll
    for (int it = 0; it < 8; it++) {
        int i = tid + it * 256;
        int row = i >> 3, ch = i & 7;
        uint32_t off = SWZ((uint32_t)((row & 127) * 128 + ch * 16));
        const char* src;
        uint32_t dst;
        if (row < 128) {
            src = (const char*)(g_A + ((size_t)(m0 + row)) * 512 + kc * 64) + ch * 16;
            dst = abase + off;
        } else {
            src = (const char*)(g_B + ((size_t)(c0 + row - 128)) * 512 + kc * 64) + ch * 16;
            dst = bbase + off;
        }
        CPA16(dst, src);
    }
    asm volatile("cp.async.commit_group;" ::: "memory");
}

__global__ void __launch_bounds__(256, 2) gemm_kernel() {
    extern __shared__ __align__(128) char smem[];
    uint32_t sb = sm2u(smem);
    const int tid = threadIdx.x;
    const int lane = tid & 31, w = tid >> 5;
    const int warp_m = w >> 2, warp_n = w & 3;
    const int m0 = blockIdx.y * 128, c0 = blockIdx.x * 128;

    float acc[4][4][4];
    #pragma unroll
    for (int i = 0; i < 4; i++)
        #pragma unroll
        for (int j = 0; j < 4; j++)
            #pragma unroll
            for (int q = 0; q < 4; q++) acc[i][j][q] = 0.f;

    const int rowA = warp_m * 64 + (lane & 15);
    const uint32_t aBase0 = (uint32_t)(rowA * 128) + ((((lane >> 4) ^ lane) & 1) << 4);
    const int rowB = warp_n * 32 + (lane & 7) + (((lane >> 4) & 1) << 3);
    const uint32_t bBase0 = (uint32_t)(rowB * 128) + ((((lane >> 3) ^ lane) & 1) << 4);
    const uint32_t kx = (uint32_t)(lane & 6) << 4;

    load_stage(sb, 0, m0, c0, 0, tid);

    for (int kc = 0; kc < 8; kc++) {
        if (kc < 7) {
            load_stage(sb, (kc + 1) & 1, m0, c0, kc + 1, tid);
            asm volatile("cp.async.wait_group 1;" ::: "memory");
        } else {
            asm volatile("cp.async.wait_group 0;" ::: "memory");
        }
        __syncthreads();
        uint32_t astage = sb + (unsigned)(kc & 1) * 32768u;
        uint32_t bstage = astage + 16384u;
        #pragma unroll
        for (int ks = 0; ks < 4; ks++) {
            uint32_t ko = ((uint32_t)(ks << 5)) ^ kx;
            uint32_t a[4][4], bfr[8];
            #pragma unroll
            for (int mi = 0; mi < 4; mi++)
                ldmx4(a[mi], astage + aBase0 + mi * 2048 + ko);
            ldmx4(&bfr[0], bstage + bBase0 + ko);
            ldmx4(&bfr[4], bstage + bBase0 + 2048 + ko);
            #pragma unroll
            for (int mi = 0; mi < 4; mi++)
                #pragma unroll
                for (int nj = 0; nj < 4; nj++)
                    mma16816(acc[mi][nj], a[mi], bfr[nj * 2], bfr[nj * 2 + 1]);
        }
        __syncthreads();
    }

    // stage this CTA's colmap slice (32 seqs x 128 cols) into smem, pitch 132
    {
        int n = tid >> 3, j = tid & 7;
        int off = c0 + j * 16;
        uint4 v = make_uint4(0u, 0u, 0u, 0u);
        if (off + 16 <= 1296)
            v = *(const uint4*)(g_colmap + (size_t)n * 1296 + off);
        uint32_t* d = (uint32_t*)(smem + n * 132 + j * 16);
        d[0] = v.x; d[1] = v.y; d[2] = v.z; d[3] = v.w;
    }
    __syncthreads();

    const int tq = lane >> 2, qi = lane & 3;
    const float EC = -32.f * LOG2E;
    const bool full = (c0 + 128 <= 1296);
    #pragma unroll
    for (int mi = 0; mi < 4; mi++) {
        #pragma unroll
        for (int half = 0; half < 2; half++) {
            int m = m0 + warp_m * 64 + mi * 16 + tq + half * 8;
            const uint8_t* cm = (const uint8_t*)smem + (m & 31) * 132 - c0;
            float s = 0.f;
            if (full) {
                #pragma unroll
                for (int nj = 0; nj < 4; nj++) {
                    int c = c0 + warp_n * 32 + nj * 8 + qi * 2;
                    float x0 = acc[mi][nj][half * 2 + 0];
                    float x1 = acc[mi][nj][half * 2 + 1];
                    s += ex2f(fmaf(x0, LOG2E, EC));
                    s += ex2f(fmaf(x1, LOG2E, EC));
                    uint8_t v0 = cm[c], v1 = cm[c + 1];
                    if (v0) g_lpraw[(size_t)m * 64 + v0 - 1] = x0;
                    if (v1) g_lpraw[(size_t)m * 64 + v1 - 1] = x1;
                }
            } else {
                #pragma unroll
                for (int nj = 0; nj < 4; nj++) {
                    int c = c0 + warp_n * 32 + nj * 8 + qi * 2;
                    float x0 = acc[mi][nj][half * 2 + 0];
                    float x1 = acc[mi][nj][half * 2 + 1];
                    if (c < 1296) {
                        s += ex2f(fmaf(x0, LOG2E, EC));
                        uint8_t v = cm[c];
                        if (v) g_lpraw[(size_t)m * 64 + v - 1] = x0;
                    }
                    if (c + 1 < 1296) {
                        s += ex2f(fmaf(x1, LOG2E, EC));
                        uint8_t v = cm[c + 1];
                        if (v) g_lpraw[(size_t)m * 64 + v - 1] = x1;
                    }
                }
            }
            s += __shfl_xor_sync(0xffffffffu, s, 1);
            s += __shfl_xor_sync(0xffffffffu, s, 2);
            if (qi == 0)
                g_psum[(size_t)m * 44 + blockIdx.x * 4 + warp_n] = s;
        }
    }
}

// ---------- K5: finalize lp = (gathered - lse) * log2e ----------
__global__ void finalize_kernel(const int* __restrict__ labeling) {
    int gw = blockIdx.x * 8 + (threadIdx.x >> 5);   // gw = t*32 + n
    int lane = threadIdx.x & 31;
    int t = gw >> 5, n = gw & 31;
    const float* P = g_psum + (size_t)gw * 44;
    float p = (lane < 22) ? (P[lane] + P[lane + 22]) : 0.f;
    #pragma unroll
    for (int o = 16; o > 0; o >>= 1) p += __shfl_xor_sync(0xffffffffu, p, o);
    float lse = 32.f + logf(p);
    float* dst = g_lp + ((size_t)n * 512 + t) * 64;
    const float* raw = g_lpraw + (size_t)gw * 64;
    #pragma unroll
    for (int r = 0; r < 2; r++) {
        int l = lane + r * 32;
        if (l < 61) {
            int ext = (l & 1) ? labeling[n * 30 + (l >> 1)] : 0;
            int v = g_colmap[n * 1296 + ext];
            dst[l] = (raw[v - 1] - lse) * LOG2E;
        } else if (l < 64) dst[l] = NEGINF;
    }
}

// ---------- K6: bidirectional CTC (fwd warp + bwd warp), log2 domain --------
__global__ void __launch_bounds__(256) ctc_kernel(const int* __restrict__ labeling,
                                                  const int* __restrict__ in_lens,
                                                  const int* __restrict__ lab_lens,
                                                  float* __restrict__ out) {
    extern __shared__ __align__(16) float2 slp[];   // [512][32] float2 = 128 KB
    __shared__ float2 bex[32];
    const int n = blockIdx.x;
    const int tid = threadIdx.x;
    uint32_t sbase = sm2u(slp);
    const char* src = (const char*)(g_lp + (size_t)n * 512 * 64);
    #pragma unroll
    for (int it = 0; it < 32; it++) {
        int i = tid + it * 256;
        CPA16(sbase + i * 16, src + i * 16);
    }
    asm volatile("cp.async.commit_group;" ::: "memory");
    asm volatile("cp.async.wait_group 0;" ::: "memory");
    __syncthreads();
    if (tid >= 64) return;

    const int wid = tid >> 5, l = tid & 31;
    const int Tlen = in_lens[n];
    const int mid = Tlen >> 1;
    const int lab = lab_lens[n];

    if (wid == 0) {
        // ---- forward: alpha for t = 0..mid ----
        int labv = (l < 30) ? labeling[n * 30 + l] : 0;
        int labp = (l >= 1 && l <= 30) ? labeling[n * 30 + l - 1] : 0;
        const bool skip = (l >= 1 && l <= 29 && labv != labp);

        float2 v0 = slp[l];
        float lo = (l == 0) ? v0.x : NEGINF;
        float hi = (l == 0) ? v0.y : NEGINF;
        float2 lp = slp[32 + l];
        const float2* prow = &slp[64 + l];
        for (int t = 1; t <= mid; t++) {
            float2 nxt = *prow; prow += 32;
            float hp = __shfl_up_sync(0xffffffffu, hi, 1);
            if (l == 0) hp = NEGINF;
            float mx1 = fmaxf(lo, hp), mn1 = fminf(lo, hp);
            float nlo = mx1 + lg2f(1.f + ex2f(mn1 - mx1)) + lp.x;
            float a3 = skip ? hp : NEGINF;
            float mxhl = fmaxf(hi, lo), mnhl = fminf(hi, lo);
            float m2 = fmaxf(mxhl, a3);
            float md = fmaxf(mnhl, fminf(mxhl, a3));
            float mn = fminf(mnhl, a3);
            float nhi = m2 + lg2f(1.f + ex2f(md - m2) + ex2f(mn - m2)) + lp.y;
            lo = nlo; hi = nhi; lp = nxt;
        }
        asm volatile("bar.sync 1, 64;" ::: "memory");
        float2 b = bex[l];
        float vlo = lo + b.x, vhi = hi + b.y;
        float mx2 = fmaxf(vlo, vhi), mn2 = fminf(vlo, vhi);
        float v = mx2 + lg2f(1.f + ex2f(mn2 - mx2));
        float mr = v;
        #pragma unroll
        for (int o = 16; o > 0; o >>= 1) mr = fmaxf(mr, __shfl_xor_sync(0xffffffffu, mr, o));
        float s = ex2f(v - mr);
        #pragma unroll
        for (int o = 16; o > 0; o >>= 1) s += __shfl_xor_sync(0xffffffffu, s, o);
        if (l == 0) {
            g_nll[n] = -(mr + lg2f(s)) * LN2;
            __threadfence();
            int ticket = atomicAdd(&g_done, 1);
            if (ticket == 31) {                         // last block: fixed-order sum
                float acc = 0.f;
                #pragma unroll
                for (int k = 0; k < 32; k++) acc += g_nll[k];
                out[0] = acc;
            }
        }
    } else {
        // ---- backward: delta_t(s) = beta_t(s)*p_t(s), t = Tlen-1 .. mid+1 ----
        int labv = (l < 30) ? labeling[n * 30 + l] : 0;
        int labn = (l < 29) ? labeling[n * 30 + l + 1] : 0;
        const bool skipb = (l <= 28) && (labn != labv);

        float2 lpl = slp[(Tlen - 1) * 32 + l];
        float lo = (l == lab)     ? lpl.x : NEGINF;     // state Ln-1 = 2*lab
        float hi = (l == lab - 1) ? lpl.y : NEGINF;     // state Ln-2 = 2*lab-1
        float2 lp = slp[(Tlen - 2) * 32 + l];
        const float2* prow = &slp[(Tlen - 3) * 32 + l];
        for (int t = Tlen - 2; t > mid; t--) {
            float2 nxt = *prow; prow -= 32;
            float dlo = __shfl_down_sync(0xffffffffu, lo, 1);
            float dhi = __shfl_down_sync(0xffffffffu, hi, 1);
            // even state: only self + s+1 (blank->blank skip never allowed)
            float mx1 = fmaxf(lo, hi), mn1 = fminf(lo, hi);
            float nlo = mx1 + lg2f(1.f + ex2f(mn1 - mx1)) + lp.x;
            // odd state: self, s+1, skip s+2
            float a3 = skipb ? dhi : NEGINF;
            float mxhl = fmaxf(hi, dlo), mnhl = fminf(hi, dlo);
            float m2 = fmaxf(mxhl, a3);
            float md = fmaxf(mnhl, fminf(mxhl, a3));
            float mn = fminf(mnhl, a3);
            float nhi = m2 + lg2f(1.f + ex2f(md - m2) + ex2f(mn - m2)) + lp.y;
            lo = nlo; hi = nhi; lp = nxt;
        }
        // transition-only step at t = mid (no lp factor)
        {
            float dlo = __shfl_down_sync(0xffffffffu, lo, 1);
            float dhi = __shfl_down_sync(0xffffffffu, hi, 1);
            float mx1 = fmaxf(lo, hi), mn1 = fminf(lo, hi);
            float tlo = mx1 + lg2f(1.f + ex2f(mn1 - mx1));
            float a3 = skipb ? dhi : NEGINF;
            float mxhl = fmaxf(hi, dlo), mnhl = fminf(hi, dlo);
            float m2 = fmaxf(mxhl, a3);
            float md = fmaxf(mnhl, fminf(mxhl, a3));
            float mn = fminf(mnhl, a3);
            float thi = m2 + lg2f(1.f + ex2f(md - m2) + ex2f(mn - m2));
            bex[l] = make_float2(tlo, thi);
        }
        asm volatile("bar.sync 1, 64;" ::: "memory");
    }
}

// ---------- launch ----------
extern "C" void kernel_launch(void* const* d_in, const int* in_sizes, int n_in,
                              void* d_out, int out_size) {
    const float* feats = (const float*)d_in[0];
    const float* weight = (const float*)d_in[1];
    const int* labeling = (const int*)d_in[2];
    const int* logit_lgts = (const int*)d_in[3];
    const int* labeling_lgts = (const int*)d_in[4];
    float* out = (float*)d_out;

    cudaFuncSetAttribute(gemm_kernel, cudaFuncAttributeMaxDynamicSharedMemorySize, 65536);
    cudaFuncSetAttribute(ctc_kernel, cudaFuncAttributeMaxDynamicSharedMemorySize, 131072);

    colsum_kernel<<<dim3(41, 8), dim3(32, 8)>>>(weight);
    wtrans_kernel<<<dim3(41, 16), dim3(32, 8)>>>(weight);
    fprep_kernel<<<2048, 256>>>(feats, labeling);
    gemm_kernel<<<dim3(11, 128), 256, 65536>>>();
    finalize_kernel<<<2048, 256>>>(labeling);
    ctc_kernel<<<32, 256, 131072>>>(labeling, logit_lgts, labeling_lgts, out);
}

// round 16
// speedup vs baseline: 1.2345x; 1.0024x over previous
#include <cuda_runtime.h>
#include <cuda_bf16.h>
#include <cstdint>

#define NEGINF -1e9f
#define SWZ(x) ((x) ^ (((x) >> 3) & 0x70))
#define LOG2E 1.4426950408889634f
#define LN2   0.6931471805599453f

// ---------- device scratch ----------
__device__ __align__(16) __nv_bfloat16 g_A[(size_t)16384 * 512];   // (t*32+n, k), 32*f/||f||
__device__ __align__(16) __nv_bfloat16 g_B[(size_t)1408 * 512];    // (c, k); rows>=1296 stay 0
__device__ float   g_part[8 * 1296];
__device__ __align__(16) uint8_t g_colmap[32 * 1296];              // value -> state slot + 1
__device__ float   g_psum[(size_t)16384 * 44];
__device__ float   g_lpraw[(size_t)16384 * 64];                    // gathered logits by slot
__device__ __align__(16) float g_lp[(size_t)32 * 512 * 64];        // (n,t,l) log2-probs
__device__ float   g_nll[32];
__device__ int     g_done;

__device__ __forceinline__ uint32_t sm2u(const void* p) {
    uint32_t a;
    asm("{ .reg .u64 t; cvta.to.shared.u64 t, %1; cvt.u32.u64 %0, t; }" : "=r"(a) : "l"(p));
    return a;
}
#define CPA16(d, s) asm volatile("cp.async.cg.shared.global [%0], [%1], 16;" :: "r"(d), "l"(s) : "memory")
__device__ __forceinline__ void ldmx4(uint32_t* r, uint32_t a) {
    asm volatile("ldmatrix.sync.aligned.m8n8.x4.shared.b16 {%0,%1,%2,%3}, [%4];"
        : "=r"(r[0]), "=r"(r[1]), "=r"(r[2]), "=r"(r[3]) : "r"(a));
}
__device__ __forceinline__ void mma16816(float* c, const uint32_t* a, uint32_t b0, uint32_t b1) {
    asm volatile("mma.sync.aligned.m16n8k16.row.col.f32.bf16.bf16.f32 "
        "{%0,%1,%2,%3},{%4,%5,%6,%7},{%8,%9},{%0,%1,%2,%3};"
        : "+f"(c[0]), "+f"(c[1]), "+f"(c[2]), "+f"(c[3])
        : "r"(a[0]), "r"(a[1]), "r"(a[2]), "r"(a[3]), "r"(b0), "r"(b1));
}
__device__ __forceinline__ float ex2f(float x) { float r; asm("ex2.approx.f32 %0, %1;" : "=f"(r) : "f"(x)); return r; }
__device__ __forceinline__ float lg2f(float x) { float r; asm("lg2.approx.f32 %0, %1;" : "=f"(r) : "f"(x)); return r; }

// ---------- K1: column sum-of-squares partials ----------
__global__ void colsum_kernel(const float* __restrict__ w) {
    __shared__ float sp[8][33];
    int c0 = blockIdx.x * 32, d0 = blockIdx.y * 64;
    int tx = threadIdx.x, ty = threadIdx.y;
    int c = c0 + tx;
    float s = 0.f;
    if (c < 1296) {
        #pragma unroll
        for (int i = 0; i < 8; i++) {
            float v = w[(size_t)(d0 + ty + i * 8) * 1296 + c];
            s += v * v;
        }
    }
    sp[ty][tx] = s;
    __syncthreads();
    if (ty == 0 && c < 1296) {
        float t = 0.f;
        #pragma unroll
        for (int i = 0; i < 8; i++) t += sp[i][tx];
        g_part[blockIdx.y * 1296 + c] = t;
    }
}

// ---------- K2: W transpose + normalize -> bf16 (c,k) ----------
__global__ void wtrans_kernel(const float* __restrict__ w) {
    __shared__ float tile[32][33];
    int c0 = blockIdx.x * 32, k0 = blockIdx.y * 32;
    int tx = threadIdx.x, ty = threadIdx.y;
    #pragma unroll
    for (int i = 0; i < 4; i++) {
        int c = c0 + tx, k = k0 + ty + i * 8;
        tile[ty + i * 8][tx] = (c < 1296) ? w[(size_t)k * 1296 + c] : 0.f;
    }
    __syncthreads();
    #pragma unroll
    for (int i = 0; i < 4; i++) {
        int c = c0 + ty + i * 8, k = k0 + tx;
        if (c < 1296) {
            float sum = 0.f;
            #pragma unroll
            for (int j = 0; j < 8; j++) sum += g_part[j * 1296 + c];
            g_B[(size_t)c * 512 + k] = __float2bfloat16(tile[tx][ty + i * 8] * rsqrtf(sum));
        }
    }
}

// ---------- K3: feats * 32/||f|| -> bf16 ; blocks 0-31 build colmap ----------
__global__ void fprep_kernel(const float* __restrict__ f, const int* __restrict__ labeling) {
    if (blockIdx.x == 0 && threadIdx.x == 0) g_done = 0;
    int gw = (blockIdx.x * blockDim.x + threadIdx.x) >> 5;
    int lane = threadIdx.x & 31;
    const float2* row = (const float2*)(f + (size_t)gw * 512);
    float2 v[8]; float s = 0.f;
    #pragma unroll
    for (int j = 0; j < 8; j++) { v[j] = row[j * 32 + lane]; s += v[j].x * v[j].x + v[j].y * v[j].y; }
    #pragma unroll
    for (int o = 16; o > 0; o >>= 1) s += __shfl_xor_sync(0xffffffffu, s, o);
    float sc = 32.f * rsqrtf(s);
    __nv_bfloat162* dst = (__nv_bfloat162*)(g_A + (size_t)gw * 512);
    #pragma unroll
    for (int j = 0; j < 8; j++) dst[j * 32 + lane] = __floats2bfloat162_rn(v[j].x * sc, v[j].y * sc);

    if (blockIdx.x < 32) {
        int n = blockIdx.x;
        uint32_t* row32 = (uint32_t*)(g_colmap + n * 1296);
        for (int i = threadIdx.x; i < 324; i += 256) row32[i] = 0;
        __syncthreads();
        if (threadIdx.x == 0) {
            uint8_t* r8 = g_colmap + n * 1296;
            r8[0] = 1;
            for (int l = 1; l < 61; l += 2) r8[labeling[n * 30 + (l >> 1)]] = (uint8_t)(l + 1);
        }
    }
}

// ---------- K4: HMMA GEMM (R4 mainloop) + smem-colmap gather epilogue -------
__device__ __forceinline__ void load_stage(uint32_t sb, int st, int m0, int c0, int kc, int tid) {
    uint32_t abase = sb + (unsigned)st * 32768u;
    uint32_t bbase = abase + 16384u;
    #pragma unroll
    for (int it = 0; it < 8; it++) {
        int i = tid + it * 256;
        int row = i >> 3, ch = i & 7;
        uint32_t off = SWZ((uint32_t)((row & 127) * 128 + ch * 16));
        const char* src;
        uint32_t dst;
        if (row < 128) {
            src = (const char*)(g_A + ((size_t)(m0 + row)) * 512 + kc * 64) + ch * 16;
            dst = abase + off;
        } else {
            src = (const char*)(g_B + ((size_t)(c0 + row - 128)) * 512 + kc * 64) + ch * 16;
            dst = bbase + off;
        }
        CPA16(dst, src);
    }
    asm volatile("cp.async.commit_group;" ::: "memory");
}

__global__ void __launch_bounds__(256, 2) gemm_kernel() {
    extern __shared__ __align__(128) char smem[];
    uint32_t sb = sm2u(smem);
    const int tid = threadIdx.x;
    const int lane = tid & 31, w = tid >> 5;
    const int warp_m = w >> 2, warp_n = w & 3;
    const int m0 = blockIdx.y * 128, c0 = blockIdx.x * 128;

    float acc[4][4][4];
    #pragma unroll
    for (int i = 0; i < 4; i++)
        #pragma unroll
        for (int j = 0; j < 4; j++)
            #pragma unroll
            for (int q = 0; q < 4; q++) acc[i][j][q] = 0.f;

    const int rowA = warp_m * 64 + (lane & 15);
    const uint32_t aBase0 = (uint32_t)(rowA * 128) + ((((lane >> 4) ^ lane) & 1) << 4);
    const int rowB = warp_n * 32 + (lane & 7) + (((lane >> 4) & 1) << 3);
    const uint32_t bBase0 = (uint32_t)(rowB * 128) + ((((lane >> 3) ^ lane) & 1) << 4);
    const uint32_t kx = (uint32_t)(lane & 6) << 4;

    load_stage(sb, 0, m0, c0, 0, tid);

    for (int kc = 0; kc < 8; kc++) {
        if (kc < 7) {
            load_stage(sb, (kc + 1) & 1, m0, c0, kc + 1, tid);
            asm volatile("cp.async.wait_group 1;" ::: "memory");
        } else {
            asm volatile("cp.async.wait_group 0;" ::: "memory");
        }
        __syncthreads();
        uint32_t astage = sb + (unsigned)(kc & 1) * 32768u;
        uint32_t bstage = astage + 16384u;
        #pragma unroll
        for (int ks = 0; ks < 4; ks++) {
            uint32_t ko = ((uint32_t)(ks << 5)) ^ kx;
            uint32_t a[4][4], bfr[8];
            #pragma unroll
            for (int mi = 0; mi < 4; mi++)
                ldmx4(a[mi], astage + aBase0 + mi * 2048 + ko);
            ldmx4(&bfr[0], bstage + bBase0 + ko);
            ldmx4(&bfr[4], bstage + bBase0 + 2048 + ko);
            #pragma unroll
            for (int mi = 0; mi < 4; mi++)
                #pragma unroll
                for (int nj = 0; nj < 4; nj++)
                    mma16816(acc[mi][nj], a[mi], bfr[nj * 2], bfr[nj * 2 + 1]);
        }
        __syncthreads();
    }

    // stage this CTA's colmap slice (32 seqs x 128 cols) into smem, pitch 132
    {
        int n = tid >> 3, j = tid & 7;
        int off = c0 + j * 16;
        uint4 v = make_uint4(0u, 0u, 0u, 0u);
        if (off + 16 <= 1296)
            v = *(const uint4*)(g_colmap + (size_t)n * 1296 + off);
        uint32_t* d = (uint32_t*)(smem + n * 132 + j * 16);
        d[0] = v.x; d[1] = v.y; d[2] = v.z; d[3] = v.w;
    }
    __syncthreads();

    const int tq = lane >> 2, qi = lane & 3;
    const float EC = -32.f * LOG2E;
    const bool full = (c0 + 128 <= 1296);
    #pragma unroll
    for (int mi = 0; mi < 4; mi++) {
        #pragma unroll
        for (int half = 0; half < 2; half++) {
            int m = m0 + warp_m * 64 + mi * 16 + tq + half * 8;
            const uint8_t* cm = (const uint8_t*)smem + (m & 31) * 132 - c0;
            float s = 0.f;
            if (full) {
                #pragma unroll
                for (int nj = 0; nj < 4; nj++) {
                    int c = c0 + warp_n * 32 + nj * 8 + qi * 2;
                    float x0 = acc[mi][nj][half * 2 + 0];
                    float x1 = acc[mi][nj][half * 2 + 1];
                    s += ex2f(fmaf(x0, LOG2E, EC));
                    s += ex2f(fmaf(x1, LOG2E, EC));
                    uint8_t v0 = cm[c], v1 = cm[c + 1];
                    if (v0) g_lpraw[(size_t)m * 64 + v0 - 1] = x0;
                    if (v1) g_lpraw[(size_t)m * 64 + v1 - 1] = x1;
                }
            } else {
                #pragma unroll
                for (int nj = 0; nj < 4; nj++) {
                    int c = c0 + warp_n * 32 + nj * 8 + qi * 2;
                    float x0 = acc[mi][nj][half * 2 + 0];
                    float x1 = acc[mi][nj][half * 2 + 1];
                    if (c < 1296) {
                        s += ex2f(fmaf(x0, LOG2E, EC));
                        uint8_t v = cm[c];
                        if (v) g_lpraw[(size_t)m * 64 + v - 1] = x0;
                    }
                    if (c + 1 < 1296) {
                        s += ex2f(fmaf(x1, LOG2E, EC));
                        uint8_t v = cm[c + 1];
                        if (v) g_lpraw[(size_t)m * 64 + v - 1] = x1;
                    }
                }
            }
            s += __shfl_xor_sync(0xffffffffu, s, 1);
            s += __shfl_xor_sync(0xffffffffu, s, 2);
            if (qi == 0)
                g_psum[(size_t)m * 44 + blockIdx.x * 4 + warp_n] = s;
        }
    }
}

// ---------- K5: finalize lp = (gathered - lse) * log2e ----------
__global__ void finalize_kernel(const int* __restrict__ labeling) {
    int gw = blockIdx.x * 8 + (threadIdx.x >> 5);   // gw = t*32 + n
    int lane = threadIdx.x & 31;
    int t = gw >> 5, n = gw & 31;
    const float* P = g_psum + (size_t)gw * 44;
    float p = (lane < 22) ? (P[lane] + P[lane + 22]) : 0.f;
    #pragma unroll
    for (int o = 16; o > 0; o >>= 1) p += __shfl_xor_sync(0xffffffffu, p, o);
    float lse = 32.f + logf(p);
    float* dst = g_lp + ((size_t)n * 512 + t) * 64;
    const float* raw = g_lpraw + (size_t)gw * 64;
    #pragma unroll
    for (int r = 0; r < 2; r++) {
        int l = lane + r * 32;
        if (l < 61) {
            int ext = (l & 1) ? labeling[n * 30 + (l >> 1)] : 0;
            int v = g_colmap[n * 1296 + ext];
            dst[l] = (raw[v - 1] - lse) * LOG2E;
        } else if (l < 64) dst[l] = NEGINF;
    }
}

// ---------- K6: bidirectional CTC (fwd warp + bwd warp), log2 domain --------
__global__ void __launch_bounds__(256) ctc_kernel(const int* __restrict__ labeling,
                                                  const int* __restrict__ in_lens,
                                                  const int* __restrict__ lab_lens,
                                                  float* __restrict__ out) {
    extern __shared__ __align__(16) float2 slp[];   // [512][32] float2 = 128 KB
    __shared__ float2 bex[32];
    const int n = blockIdx.x;
    const int tid = threadIdx.x;
    uint32_t sbase = sm2u(slp);
    const char* src = (const char*)(g_lp + (size_t)n * 512 * 64);
    #pragma unroll
    for (int it = 0; it < 32; it++) {
        int i = tid + it * 256;
        CPA16(sbase + i * 16, src + i * 16);
    }
    asm volatile("cp.async.commit_group;" ::: "memory");
    asm volatile("cp.async.wait_group 0;" ::: "memory");
    __syncthreads();
    if (tid >= 64) return;

    const int wid = tid >> 5, l = tid & 31;
    const int Tlen = in_lens[n];
    const int mid = Tlen >> 1;
    const int lab = lab_lens[n];

    if (wid == 0) {
        // ---- forward: alpha for t = 0..mid ----
        int labv = (l < 30) ? labeling[n * 30 + l] : 0;
        int labp = (l >= 1 && l <= 30) ? labeling[n * 30 + l - 1] : 0;
        const bool skip = (l >= 1 && l <= 29 && labv != labp);

        float2 v0 = slp[l];
        float lo = (l == 0) ? v0.x : NEGINF;
        float hi = (l == 0) ? v0.y : NEGINF;
        float2 lp = slp[32 + l];
        const float2* prow = &slp[64 + l];
        for (int t = 1; t <= mid; t++) {
            float2 nxt = *prow; prow += 32;
            float hp = __shfl_up_sync(0xffffffffu, hi, 1);
            if (l == 0) hp = NEGINF;
            float mx1 = fmaxf(lo, hp), mn1 = fminf(lo, hp);
            float nlo = mx1 + lg2f(1.f + ex2f(mn1 - mx1)) + lp.x;
            float a3 = skip ? hp : NEGINF;
            float mxhl = fmaxf(hi, lo), mnhl = fminf(hi, lo);
            float m2 = fmaxf(mxhl, a3);
            float md = fmaxf(mnhl, fminf(mxhl, a3));
            float mn = fminf(mnhl, a3);
            float nhi = m2 + lg2f(1.f + ex2f(md - m2) + ex2f(mn - m2)) + lp.y;
            lo = nlo; hi = nhi; lp = nxt;
        }
        asm volatile("bar.sync 1, 64;" ::: "memory");
        float2 b = bex[l];
        float vlo = lo + b.x, vhi = hi + b.y;
        float mx2 = fmaxf(vlo, vhi), mn2 = fminf(vlo, vhi);
        float v = mx2 + lg2f(1.f + ex2f(mn2 - mx2));
        float mr = v;
        #pragma unroll
        for (int o = 16; o > 0; o >>= 1) mr = fmaxf(mr, __shfl_xor_sync(0xffffffffu, mr, o));
        float s = ex2f(v - mr);
        #pragma unroll
        for (int o = 16; o > 0; o >>= 1) s += __shfl_xor_sync(0xffffffffu, s, o);
        if (l == 0) {
            g_nll[n] = -(mr + lg2f(s)) * LN2;
            __threadfence();
            int ticket = atomicAdd(&g_done, 1);
            if (ticket == 31) {                         // last block: fixed-order sum
                float acc = 0.f;
                #pragma unroll
                for (int k = 0; k < 32; k++) acc += g_nll[k];
                out[0] = acc;
            }
        }
    } else {
        // ---- backward: delta_t(s) = beta_t(s)*p_t(s), t = Tlen-1 .. mid+1 ----
        int labv = (l < 30) ? labeling[n * 30 + l] : 0;
        int labn = (l < 29) ? labeling[n * 30 + l + 1] : 0;
        const bool skipb = (l <= 28) && (labn != labv);

        float2 lpl = slp[(Tlen - 1) * 32 + l];
        float lo = (l == lab)     ? lpl.x : NEGINF;     // state Ln-1 = 2*lab
        float hi = (l == lab - 1) ? lpl.y : NEGINF;     // state Ln-2 = 2*lab-1
        float2 lp = slp[(Tlen - 2) * 32 + l];
        const float2* prow = &slp[(Tlen - 3) * 32 + l];
        for (int t = Tlen - 2; t > mid; t--) {
            float2 nxt = *prow; prow -= 32;
            float dlo = __shfl_down_sync(0xffffffffu, lo, 1);
            float dhi = __shfl_down_sync(0xffffffffu, hi, 1);
            // even state: only self + s+1 (blank->blank skip never allowed)
            float mx1 = fmaxf(lo, hi), mn1 = fminf(lo, hi);
            float nlo = mx1 + lg2f(1.f + ex2f(mn1 - mx1)) + lp.x;
            // odd state: self, s+1, skip s+2
            float a3 = skipb ? dhi : NEGINF;
            float mxhl = fmaxf(hi, dlo), mnhl = fminf(hi, dlo);
            float m2 = fmaxf(mxhl, a3);
            float md = fmaxf(mnhl, fminf(mxhl, a3));
            float mn = fminf(mnhl, a3);
            float nhi = m2 + lg2f(1.f + ex2f(md - m2) + ex2f(mn - m2)) + lp.y;
            lo = nlo; hi = nhi; lp = nxt;
        }
        // transition-only step at t = mid (no lp factor)
        {
            float dlo = __shfl_down_sync(0xffffffffu, lo, 1);
            float dhi = __shfl_down_sync(0xffffffffu, hi, 1);
            float mx1 = fmaxf(lo, hi), mn1 = fminf(lo, hi);
            float tlo = mx1 + lg2f(1.f + ex2f(mn1 - mx1));
            float a3 = skipb ? dhi : NEGINF;
            float mxhl = fmaxf(hi, dlo), mnhl = fminf(hi, dlo);
            float m2 = fmaxf(mxhl, a3);
            float md = fmaxf(mnhl, fminf(mxhl, a3));
            float mn = fminf(mnhl, a3);
            float thi = m2 + lg2f(1.f + ex2f(md - m2) + ex2f(mn - m2));
            bex[l] = make_float2(tlo, thi);
        }
        asm volatile("bar.sync 1, 64;" ::: "memory");
    }
}

// ---------- launch ----------
extern "C" void kernel_launch(void* const* d_in, const int* in_sizes, int n_in,
                              void* d_out, int out_size) {
    const float* feats = (const float*)d_in[0];
    const float* weight = (const float*)d_in[1];
    const int* labeling = (const int*)d_in[2];
    const int* logit_lgts = (const int*)d_in[3];
    const int* labeling_lgts = (const int*)d_in[4];
    float* out = (float*)d_out;

    cudaFuncSetAttribute(gemm_kernel, cudaFuncAttributeMaxDynamicSharedMemorySize, 65536);
    cudaFuncSetAttribute(ctc_kernel, cudaFuncAttributeMaxDynamicSharedMemorySize, 131072);

    colsum_kernel<<<dim3(41, 8), dim3(32, 8)>>>(weight);
    wtrans_kernel<<<dim3(41, 16), dim3(32, 8)>>>(weight);
    fprep_kernel<<<2048, 256>>>(feats, labeling);
    gemm_kernel<<<dim3(11, 128), 256, 65536>>>();
    finalize_kernel<<<2048, 256>>>(labeling);
    ctc_kernel<<<32, 256, 131072>>>(labeling, logit_lgts, labeling_lgts, out);
}